// round 5
// baseline (speedup 1.0000x reference)
#include <cuda_runtime.h>
#include <math.h>

#define BSZ 2
#define SEQ 2048
#define DM  1024
#define NH  16
#define DH  64
#define DFF 4096
#define MR  (BSZ*SEQ)   // 4096 rows

// ---------------- scratch (device globals: allocation-free) ----------------
__device__ float g_h  [MR*DM];
__device__ float g_q  [MR*DM];
__device__ float g_k  [MR*DM];
__device__ float g_v  [MR*DM];
__device__ float g_c  [MR*NH];
__device__ float g_ctx[MR*DM];
__device__ float g_x1 [MR*DM];
__device__ float g_h2 [MR*DM];
__device__ float g_ff [MR*DFF];

// ---------------- LayerNorm: one block per row of 1024 ----------------
__global__ __launch_bounds__(256) void ln_kernel(
    const float* __restrict__ x, const float* __restrict__ g,
    const float* __restrict__ b, float* __restrict__ out)
{
    int row = blockIdx.x;
    int tid = threadIdx.x;
    const float4* xr = (const float4*)(x + (size_t)row*DM);
    float4 v = xr[tid];
    float s  = v.x + v.y + v.z + v.w;
    float sq = v.x*v.x + v.y*v.y + v.z*v.z + v.w*v.w;
    #pragma unroll
    for (int o = 16; o; o >>= 1) {
        s  += __shfl_xor_sync(0xffffffffu, s,  o);
        sq += __shfl_xor_sync(0xffffffffu, sq, o);
    }
    __shared__ float rs[8], rq[8], fin[2];
    int wid = tid >> 5, lane = tid & 31;
    if (lane == 0) { rs[wid] = s; rq[wid] = sq; }
    __syncthreads();
    if (tid == 0) {
        float ts = 0.f, tq = 0.f;
        #pragma unroll
        for (int i = 0; i < 8; i++) { ts += rs[i]; tq += rq[i]; }
        float mu = ts * (1.0f/DM);
        float var = tq * (1.0f/DM) - mu*mu;
        fin[0] = mu;
        fin[1] = rsqrtf(var + 1e-5f);
    }
    __syncthreads();
    float mu = fin[0], rstd = fin[1];
    float4 g4 = ((const float4*)g)[tid];
    float4 b4 = ((const float4*)b)[tid];
    float4 o4;
    o4.x = (v.x - mu)*rstd*g4.x + b4.x;
    o4.y = (v.y - mu)*rstd*g4.y + b4.y;
    o4.z = (v.z - mu)*rstd*g4.z + b4.z;
    o4.w = (v.w - mu)*rstd*g4.w + b4.w;
    ((float4*)(out + (size_t)row*DM))[tid] = o4;
}

// ---------------- generic SGEMM 128x128x16, 8x8 microtile ----------------
// ep: 0 = C = AB + bias ; 1 = + bias + res ; 2 = gelu(AB + bias)
__global__ __launch_bounds__(256) void sgemm_kernel(
    const float* __restrict__ A, const float* __restrict__ B,
    const float* __restrict__ bias, const float* __restrict__ res,
    float* __restrict__ C, int M, int N, int K, int ep)
{
    __shared__ float As[16][128];
    __shared__ float Bs[16][128];
    int tid = threadIdx.x;
    int m0 = blockIdx.y * 128, n0 = blockIdx.x * 128;
    int ty = tid >> 4, tx = tid & 15;

    float acc[8][8];
    #pragma unroll
    for (int i = 0; i < 8; i++)
        #pragma unroll
        for (int j = 0; j < 8; j++) acc[i][j] = 0.f;

    for (int k0 = 0; k0 < K; k0 += 16) {
        #pragma unroll
        for (int rep = 0; rep < 2; rep++) {
            int f = tid + rep*256;                  // 0..511
            int arow = f >> 2, k4 = (f & 3) * 4;
            float4 a = *(const float4*)(A + (size_t)(m0+arow)*K + k0 + k4);
            As[k4+0][arow] = a.x; As[k4+1][arow] = a.y;
            As[k4+2][arow] = a.z; As[k4+3][arow] = a.w;
            int brow = f >> 5, c4 = (f & 31) * 4;
            *(float4*)(&Bs[brow][c4]) =
                *(const float4*)(B + (size_t)(k0+brow)*N + n0 + c4);
        }
        __syncthreads();
        #pragma unroll
        for (int kk = 0; kk < 16; kk++) {
            float a[8], bb[8];
            *(float4*)(a)   = *(float4*)(&As[kk][ty*8]);
            *(float4*)(a+4) = *(float4*)(&As[kk][ty*8+4]);
            *(float4*)(bb)   = *(float4*)(&Bs[kk][tx*8]);
            *(float4*)(bb+4) = *(float4*)(&Bs[kk][tx*8+4]);
            #pragma unroll
            for (int i = 0; i < 8; i++)
                #pragma unroll
                for (int j = 0; j < 8; j++)
                    acc[i][j] += a[i] * bb[j];
        }
        __syncthreads();
    }

    #pragma unroll
    for (int i = 0; i < 8; i++) {
        int m = m0 + ty*8 + i;
        #pragma unroll
        for (int j = 0; j < 8; j += 4) {
            int n = n0 + tx*8 + j;
            float4 bi = *(const float4*)(bias + n);
            float4 r;
            r.x = acc[i][j+0] + bi.x;
            r.y = acc[i][j+1] + bi.y;
            r.z = acc[i][j+2] + bi.z;
            r.w = acc[i][j+3] + bi.w;
            if (ep == 1) {
                float4 rr = *(const float4*)(res + (size_t)m*N + n);
                r.x += rr.x; r.y += rr.y; r.z += rr.z; r.w += rr.w;
            } else if (ep == 2) {
                r.x = 0.5f*r.x*(1.0f + erff(r.x*0.70710678118654752f));
                r.y = 0.5f*r.y*(1.0f + erff(r.y*0.70710678118654752f));
                r.z = 0.5f*r.z*(1.0f + erff(r.z*0.70710678118654752f));
                r.w = 0.5f*r.w*(1.0f + erff(r.w*0.70710678118654752f));
            }
            *(float4*)(C + (size_t)m*N + n) = r;
        }
    }
}

// ---------------- forget gate: logf = log_sigmoid(h @ wf + bf) ----------------
__global__ __launch_bounds__(256) void fgate_kernel(
    const float* __restrict__ h, const float* __restrict__ wf,
    const float* __restrict__ bf, float* __restrict__ c)
{
    int row = blockIdx.x;
    int head = threadIdx.x >> 4, lane = threadIdx.x & 15;
    float s = 0.f;
    for (int d = lane; d < DM; d += 16)
        s += h[(size_t)row*DM + d] * wf[d*NH + head];
    #pragma unroll
    for (int o = 8; o; o >>= 1) s += __shfl_xor_sync(0xffffffffu, s, o);
    if (lane == 0) {
        float z = s + bf[head];
        // stable log-sigmoid
        c[row*NH + head] = fminf(z, 0.f) - log1pf(expf(-fabsf(z)));
    }
}

// ---------------- cumulative sum of log-decay per (b, h) ----------------
__global__ void cumsum_kernel(float* __restrict__ c)
{
    int t = threadIdx.x;
    if (t >= BSZ*NH) return;
    int b = t / NH, h = t % NH;
    float acc = 0.f;
    for (int s = 0; s < SEQ; s++) {
        int idx = (b*SEQ + s)*NH + h;
        acc += c[idx];
        c[idx] = acc;
    }
}

// ---------------- flash attention w/ forgetting decay ----------------
// grid (SEQ/64, NH, BSZ), 256 threads, dynamic smem 66048 B
__global__ __launch_bounds__(256) void flash_kernel(
    const float* __restrict__ Q, const float* __restrict__ K,
    const float* __restrict__ V, const float* __restrict__ Cd,
    float* __restrict__ O)
{
    extern __shared__ float sm[];
    float* Qt = sm;           // [d][r] 64x64
    float* Kt = sm + 4096;    // [d][c] 64x64
    float* Vs = sm + 8192;    // [kk][c] 64x64
    float* Ps = sm + 12288;   // [r][kk] 64x64
    float* ci = sm + 16384;   // 64
    float* cj = sm + 16448;   // 64

    int tid = threadIdx.x, ty = tid >> 4, tx = tid & 15;
    int r0 = ty*4, c0 = tx*4;
    int b = blockIdx.z, h = blockIdx.y, i0 = blockIdx.x * 64;
    int qbase = b*SEQ + i0;
    const float scale = 0.125f;   // 1/sqrt(64)

    #pragma unroll
    for (int rep = 0; rep < 4; rep++) {
        int f = tid + rep*256;            // 0..1023 float4 slots
        int r = f >> 4, d4 = (f & 15) * 4;
        float4 qv = *(const float4*)(Q + (size_t)(qbase+r)*DM + h*64 + d4);
        Qt[(d4+0)*64 + r] = qv.x; Qt[(d4+1)*64 + r] = qv.y;
        Qt[(d4+2)*64 + r] = qv.z; Qt[(d4+3)*64 + r] = qv.w;
    }
    if (tid < 64) ci[tid] = Cd[(qbase+tid)*NH + h];

    float m_run[4], l_run[4], o[4][4];
    #pragma unroll
    for (int i = 0; i < 4; i++) {
        m_run[i] = -1e38f; l_run[i] = 0.f;
        #pragma unroll
        for (int j = 0; j < 4; j++) o[i][j] = 0.f;
    }

    for (int j0 = 0; j0 <= i0; j0 += 64) {
        __syncthreads();   // previous tile fully consumed
        int kbase = b*SEQ + j0;
        #pragma unroll
        for (int rep = 0; rep < 4; rep++) {
            int f = tid + rep*256;
            int r = f >> 4, d4 = (f & 15) * 4;
            float4 kv = *(const float4*)(K + (size_t)(kbase+r)*DM + h*64 + d4);
            Kt[(d4+0)*64 + r] = kv.x; Kt[(d4+1)*64 + r] = kv.y;
            Kt[(d4+2)*64 + r] = kv.z; Kt[(d4+3)*64 + r] = kv.w;
            float4 vv = *(const float4*)(V + (size_t)(kbase+r)*DM + h*64 + d4);
            *(float4*)(&Vs[r*64 + d4]) = vv;
        }
        if (tid < 64) cj[tid] = Cd[(kbase+tid)*NH + h];
        __syncthreads();

        // S = Q K^T
        float acc[4][4];
        #pragma unroll
        for (int i = 0; i < 4; i++)
            #pragma unroll
            for (int j = 0; j < 4; j++) acc[i][j] = 0.f;
        #pragma unroll
        for (int d = 0; d < 64; d++) {
            float4 qa = *(float4*)(&Qt[d*64 + r0]);
            float4 kb = *(float4*)(&Kt[d*64 + c0]);
            acc[0][0] += qa.x*kb.x; acc[0][1] += qa.x*kb.y; acc[0][2] += qa.x*kb.z; acc[0][3] += qa.x*kb.w;
            acc[1][0] += qa.y*kb.x; acc[1][1] += qa.y*kb.y; acc[1][2] += qa.y*kb.z; acc[1][3] += qa.y*kb.w;
            acc[2][0] += qa.z*kb.x; acc[2][1] += qa.z*kb.y; acc[2][2] += qa.z*kb.z; acc[2][3] += qa.z*kb.w;
            acc[3][0] += qa.w*kb.x; acc[3][1] += qa.w*kb.y; acc[3][2] += qa.w*kb.z; acc[3][3] += qa.w*kb.w;
        }

        bool diag = (j0 == i0);
        #pragma unroll
        for (int i = 0; i < 4; i++) {
            float crow = ci[r0+i];
            float s[4];
            #pragma unroll
            for (int j = 0; j < 4; j++) {
                s[j] = acc[i][j]*scale + crow - cj[c0+j];
                if (diag && (c0+j > r0+i)) s[j] = -1e30f;
            }
            float tm = fmaxf(fmaxf(s[0], s[1]), fmaxf(s[2], s[3]));
            #pragma unroll
            for (int off = 8; off; off >>= 1)
                tm = fmaxf(tm, __shfl_xor_sync(0xffffffffu, tm, off));
            float nm = fmaxf(m_run[i], tm);
            float p[4], tl;
            p[0] = __expf(s[0]-nm); p[1] = __expf(s[1]-nm);
            p[2] = __expf(s[2]-nm); p[3] = __expf(s[3]-nm);
            tl = p[0]+p[1]+p[2]+p[3];
            #pragma unroll
            for (int off = 8; off; off >>= 1)
                tl += __shfl_xor_sync(0xffffffffu, tl, off);
            float sc = __expf(m_run[i] - nm);
            l_run[i] = l_run[i]*sc + tl;
            m_run[i] = nm;
            #pragma unroll
            for (int j = 0; j < 4; j++) o[i][j] *= sc;
            *(float4*)(&Ps[(r0+i)*64 + c0]) = make_float4(p[0], p[1], p[2], p[3]);
        }
        __syncthreads();

        // O += P V
        #pragma unroll
        for (int kk = 0; kk < 64; kk++) {
            float4 bv = *(float4*)(&Vs[kk*64 + c0]);
            float a0 = Ps[(r0+0)*64 + kk];
            float a1 = Ps[(r0+1)*64 + kk];
            float a2 = Ps[(r0+2)*64 + kk];
            float a3 = Ps[(r0+3)*64 + kk];
            o[0][0] += a0*bv.x; o[0][1] += a0*bv.y; o[0][2] += a0*bv.z; o[0][3] += a0*bv.w;
            o[1][0] += a1*bv.x; o[1][1] += a1*bv.y; o[1][2] += a1*bv.z; o[1][3] += a1*bv.w;
            o[2][0] += a2*bv.x; o[2][1] += a2*bv.y; o[2][2] += a2*bv.z; o[2][3] += a2*bv.w;
            o[3][0] += a3*bv.x; o[3][1] += a3*bv.y; o[3][2] += a3*bv.z; o[3][3] += a3*bv.w;
        }
    }

    #pragma unroll
    for (int i = 0; i < 4; i++) {
        float inv = 1.0f / l_run[i];
        float4 ov = make_float4(o[i][0]*inv, o[i][1]*inv, o[i][2]*inv, o[i][3]*inv);
        *(float4*)(&O[(size_t)(qbase + r0 + i)*DM + h*64 + c0]) = ov;
    }
}

// ---------------- orchestration ----------------
extern "C" void kernel_launch(void* const* d_in, const int* in_sizes, int n_in,
                              void* d_out, int out_size)
{
    const float* x     = (const float*)d_in[0];
    const float* ln1_g = (const float*)d_in[1];
    const float* ln1_b = (const float*)d_in[2];
    const float* wq    = (const float*)d_in[3];
    const float* bq    = (const float*)d_in[4];
    const float* wk    = (const float*)d_in[5];
    const float* bk    = (const float*)d_in[6];
    const float* wv    = (const float*)d_in[7];
    const float* bv    = (const float*)d_in[8];
    const float* wo    = (const float*)d_in[9];
    const float* bo    = (const float*)d_in[10];
    const float* wf    = (const float*)d_in[11];
    const float* bf    = (const float*)d_in[12];
    const float* ln2_g = (const float*)d_in[13];
    const float* ln2_b = (const float*)d_in[14];
    const float* w1    = (const float*)d_in[15];
    const float* b1    = (const float*)d_in[16];
    const float* w2    = (const float*)d_in[17];
    const float* b2    = (const float*)d_in[18];
    float* out = (float*)d_out;

    float *ph, *pq, *pk, *pv, *pc, *pctx, *px1, *ph2, *pff;
    cudaGetSymbolAddress((void**)&ph,   g_h);
    cudaGetSymbolAddress((void**)&pq,   g_q);
    cudaGetSymbolAddress((void**)&pk,   g_k);
    cudaGetSymbolAddress((void**)&pv,   g_v);
    cudaGetSymbolAddress((void**)&pc,   g_c);
    cudaGetSymbolAddress((void**)&pctx, g_ctx);
    cudaGetSymbolAddress((void**)&px1,  g_x1);
    cudaGetSymbolAddress((void**)&ph2,  g_h2);
    cudaGetSymbolAddress((void**)&pff,  g_ff);

    // 1. h = LN1(x)
    ln_kernel<<<MR, 256>>>(x, ln1_g, ln1_b, ph);

    // 2. q, k, v
    dim3 gD(DM/128, MR/128);
    sgemm_kernel<<<gD, 256>>>(ph, wq, bq, nullptr, pq, MR, DM, DM, 0);
    sgemm_kernel<<<gD, 256>>>(ph, wk, bk, nullptr, pk, MR, DM, DM, 0);
    sgemm_kernel<<<gD, 256>>>(ph, wv, bv, nullptr, pv, MR, DM, DM, 0);

    // 3. forget gates + cumulative log-decay
    fgate_kernel<<<MR, 256>>>(ph, wf, bf, pc);
    cumsum_kernel<<<1, 32>>>(pc);

    // 4. flash attention with decay bias
    const int FLASH_SMEM = (4*4096 + 128) * (int)sizeof(float);   // 66048 B
    cudaFuncSetAttribute(flash_kernel, cudaFuncAttributeMaxDynamicSharedMemorySize, FLASH_SMEM);
    flash_kernel<<<dim3(SEQ/64, NH, BSZ), 256, FLASH_SMEM>>>(pq, pk, pv, pc, pctx);

    // 5. x1 = x + ctx @ wo + bo
    sgemm_kernel<<<gD, 256>>>(pctx, wo, bo, x, px1, MR, DM, DM, 1);

    // 6. h2 = LN2(x1)
    ln_kernel<<<MR, 256>>>(px1, ln2_g, ln2_b, ph2);

    // 7. ff = gelu(h2 @ w1 + b1)
    sgemm_kernel<<<dim3(DFF/128, MR/128), 256>>>(ph2, w1, b1, nullptr, pff, MR, DFF, DM, 2);

    // 8. out = x1 + ff @ w2 + b2
    sgemm_kernel<<<gD, 256>>>(pff, w2, b2, px1, out, MR, DM, DFF, 1);
}

// round 17
// speedup vs baseline: 2.0777x; 2.0777x over previous
#include <cuda_runtime.h>
#include <cuda_bf16.h>
#include <cstdint>
#include <cstddef>
#include <math.h>

#define BSZ 2
#define SEQ 2048
#define DM  1024
#define NH  16
#define DH  64
#define DFF 4096
#define MR  (BSZ*SEQ)

__device__ float g_h  [MR*DM];
__device__ float g_q  [MR*DM];
__device__ float g_k  [MR*DM];
__device__ float g_v  [MR*DM];
__device__ float g_c  [MR*NH];
__device__ float g_ctx[MR*DM];
__device__ float g_x1 [MR*DM];
__device__ float g_h2 [MR*DM];
__device__ float g_ff [MR*DFF];

__global__ __launch_bounds__(256) void ln_kernel(
    const float* __restrict__ x, const float* __restrict__ g,
    const float* __restrict__ b, float* __restrict__ out)
{
    int row = blockIdx.x;
    int tid = threadIdx.x;
    const float4* xr = (const float4*)(x + (size_t)row*DM);
    float4 v = xr[tid];
    float s  = v.x + v.y + v.z + v.w;
    float sq = v.x*v.x + v.y*v.y + v.z*v.z + v.w*v.w;
    #pragma unroll
    for (int o = 16; o; o >>= 1) {
        s  += __shfl_xor_sync(0xffffffffu, s,  o);
        sq += __shfl_xor_sync(0xffffffffu, sq, o);
    }
    __shared__ float rs[8];
    __shared__ float rq[8];
    __shared__ float fin[2];
    int wid = tid >> 5;
    int lane = tid & 31;
    if (lane == 0) { rs[wid] = s; rq[wid] = sq; }
    __syncthreads();
    if (tid == 0) {
        float ts = 0.f, tq = 0.f;
        #pragma unroll
        for (int i = 0; i < 8; i++) { ts += rs[i]; tq += rq[i]; }
        float mu = ts * (1.0f/DM);
        float var = tq * (1.0f/DM) - mu*mu;
        fin[0] = mu;
        fin[1] = rsqrtf(var + 1e-5f);
    }
    __syncthreads();
    float mu = fin[0];
    float rstd = fin[1];
    float4 g4 = ((const float4*)g)[tid];
    float4 b4 = ((const float4*)b)[tid];
    float4 o4;
    o4.x = (v.x - mu)*rstd*g4.x + b4.x;
    o4.y = (v.y - mu)*rstd*g4.y + b4.y;
    o4.z = (v.z - mu)*rstd*g4.z + b4.z;
    o4.w = (v.w - mu)*rstd*g4.w + b4.w;
    ((float4*)(out + (size_t)row*DM))[tid] = o4;
}

__device__ __forceinline__ void ldsm4(uint32_t* r, uint32_t addr)
{
    asm volatile("ldmatrix.sync.aligned.m8n8.x4.shared.b16 {%0,%1,%2,%3}, [%4];"
        : "=r"(r[0]), "=r"(r[1]), "=r"(r[2]), "=r"(r[3]) : "r"(addr));
}

__device__ __forceinline__ void ldsm4t(uint32_t* r, uint32_t addr)
{
    asm volatile("ldmatrix.sync.aligned.m8n8.x4.trans.shared.b16 {%0,%1,%2,%3}, [%4];"
        : "=r"(r[0]), "=r"(r[1]), "=r"(r[2]), "=r"(r[3]) : "r"(addr));
}

__device__ __forceinline__ void mma16816(float* c, const uint32_t* a,
                                         uint32_t b0, uint32_t b1)
{
    asm volatile("mma.sync.aligned.m16n8k16.row.col.f32.bf16.bf16.f32 "
        "{%0,%1,%2,%3}, {%4,%5,%6,%7}, {%8,%9}, {%0,%1,%2,%3};"
        : "+f"(c[0]), "+f"(c[1]), "+f"(c[2]), "+f"(c[3])
        : "r"(a[0]), "r"(a[1]), "r"(a[2]), "r"(a[3]), "r"(b0), "r"(b1));
}

__device__ __forceinline__ void split_store(
    __nv_bfloat16* __restrict__ H, __nv_bfloat16* __restrict__ L,
    int off, float x, float y)
{
    __nv_bfloat16 hx = __float2bfloat16(x);
    __nv_bfloat16 hy = __float2bfloat16(y);
    __nv_bfloat16 lx = __float2bfloat16(x - __bfloat162float(hx));
    __nv_bfloat16 ly = __float2bfloat16(y - __bfloat162float(hy));
    *(__nv_bfloat162*)&H[off] = __halves2bfloat162(hx, hy);
    *(__nv_bfloat162*)&L[off] = __halves2bfloat162(lx, ly);
}

__global__ __launch_bounds__(256) void bgemm_kernel(
    const float* __restrict__ A, const float* __restrict__ B,
    const float* __restrict__ bias, const float* __restrict__ res,
    float* __restrict__ C, int M, int N, int K, int ep)
{
    const int SA = 40;
    const int SB = 136;
    __shared__ __nv_bfloat16 Ah[128*40];
    __shared__ __nv_bfloat16 Al[128*40];
    __shared__ __nv_bfloat16 Bh[32*136];
    __shared__ __nv_bfloat16 Bl[32*136];

    int tid  = threadIdx.x;
    int m0   = blockIdx.y * 128;
    int n0   = blockIdx.x * 128;
    int lane = tid & 31;
    int warp = tid >> 5;
    int wm   = (warp >> 2) * 64;
    int wn   = (warp & 3) * 32;

    float acc[4][4][4];
    #pragma unroll
    for (int i = 0; i < 4; i++) {
        #pragma unroll
        for (int j = 0; j < 4; j++) {
            #pragma unroll
            for (int r = 0; r < 4; r++) acc[i][j][r] = 0.f;
        }
    }

    float4 ra[4];
    float4 rb[4];
    #pragma unroll
    for (int r = 0; r < 4; r++) {
        int f = tid + r*256;
        ra[r] = *(const float4*)(A + (size_t)(m0 + (f>>3))*K + ((f&7)<<2));
        rb[r] = *(const float4*)(B + (size_t)(f>>5)*N + n0 + ((f&31)<<2));
    }

    uint32_t ah_base = (uint32_t)__cvta_generic_to_shared(Ah);
    uint32_t al_base = (uint32_t)__cvta_generic_to_shared(Al);
    uint32_t bh_base = (uint32_t)__cvta_generic_to_shared(Bh);
    uint32_t bl_base = (uint32_t)__cvta_generic_to_shared(Bl);

    for (int k0 = 0; k0 < K; k0 += 32) {
        #pragma unroll
        for (int r = 0; r < 4; r++) {
            int f = tid + r*256;
            int arow = f >> 3;
            int ak = (f & 7) << 2;
            split_store(Ah, Al, arow*SA + ak,     ra[r].x, ra[r].y);
            split_store(Ah, Al, arow*SA + ak + 2, ra[r].z, ra[r].w);
            int brow = f >> 5;
            int bn = (f & 31) << 2;
            split_store(Bh, Bl, brow*SB + bn,     rb[r].x, rb[r].y);
            split_store(Bh, Bl, brow*SB + bn + 2, rb[r].z, rb[r].w);
        }
        __syncthreads();

        if (k0 + 32 < K) {
            #pragma unroll
            for (int r = 0; r < 4; r++) {
                int f = tid + r*256;
                ra[r] = *(const float4*)(A + (size_t)(m0 + (f>>3))*K + k0 + 32 + ((f&7)<<2));
                rb[r] = *(const float4*)(B + (size_t)(k0 + 32 + (f>>5))*N + n0 + ((f&31)<<2));
            }
        }

        #pragma unroll
        for (int kk = 0; kk < 2; kk++) {
            int k16 = kk * 16;
            uint32_t a_off = (uint32_t)(((wm + (lane & 15))*SA + k16 + ((lane >> 4) << 3)) * 2);
            uint32_t b_off = (uint32_t)(((k16 + (lane & 15))*SB + wn + ((lane >> 4) << 3)) * 2);

            uint32_t ahr[4][4];
            uint32_t alr[4][4];
            #pragma unroll
            for (int mt = 0; mt < 4; mt++) {
                ldsm4(ahr[mt], ah_base + a_off + mt*16*SA*2);
                ldsm4(alr[mt], al_base + a_off + mt*16*SA*2);
            }
            uint32_t bhr[8];
            uint32_t blr[8];
            ldsm4t(&bhr[0], bh_base + b_off);
            ldsm4t(&bhr[4], bh_base + b_off + 32);
            ldsm4t(&blr[0], bl_base + b_off);
            ldsm4t(&blr[4], bl_base + b_off + 32);

            #pragma unroll
            for (int mt = 0; mt < 4; mt++) {
                #pragma unroll
                for (int nt = 0; nt < 4; nt++) {
                    mma16816(acc[mt][nt], ahr[mt], bhr[nt*2], bhr[nt*2+1]);
                    mma16816(acc[mt][nt], alr[mt], bhr[nt*2], bhr[nt*2+1]);
                    mma16816(acc[mt][nt], ahr[mt], blr[nt*2], blr[nt*2+1]);
                }
            }
        }
        __syncthreads();
    }

    #pragma unroll
    for (int mt = 0; mt < 4; mt++) {
        int mrow = m0 + wm + mt*16 + (lane >> 2);
        #pragma unroll
        for (int nt = 0; nt < 4; nt++) {
            int col = n0 + wn + nt*8 + ((lane & 3) << 1);
            float2 bi = *(const float2*)(bias + col);
            #pragma unroll
            for (int rr = 0; rr < 2; rr++) {
                int m = mrow + rr*8;
                float vx = acc[mt][nt][rr*2]     + bi.x;
                float vy = acc[mt][nt][rr*2 + 1] + bi.y;
                if (ep == 1) {
                    float2 rv = *(const float2*)(res + (size_t)m*N + col);
                    vx += rv.x;
                    vy += rv.y;
                } else if (ep == 2) {
                    vx = 0.5f*vx*(1.0f + erff(vx*0.70710678118654752f));
                    vy = 0.5f*vy*(1.0f + erff(vy*0.70710678118654752f));
                }
                *(float2*)(C + (size_t)m*N + col) = make_float2(vx, vy);
            }
        }
    }
}

__global__ __launch_bounds__(256) void fgate_kernel(
    const float* __restrict__ h, const float* __restrict__ wf,
    const float* __restrict__ bf, float* __restrict__ c)
{
    int row = blockIdx.x;
    int head = threadIdx.x >> 4;
    int lane = threadIdx.x & 15;
    float s = 0.f;
    for (int d = lane; d < DM; d += 16)
        s += h[(size_t)row*DM + d] * wf[d*NH + head];
    #pragma unroll
    for (int o = 8; o; o >>= 1) s += __shfl_xor_sync(0xffffffffu, s, o);
    if (lane == 0) {
        float z = s + bf[head];
        c[row*NH + head] = fminf(z, 0.f) - log1pf(expf(-fabsf(z)));
    }
}

__global__ __launch_bounds__(256) void cumsum_kernel(float* __restrict__ c)
{
    int bh = blockIdx.x;
    int b = bh / NH;
    int h = bh % NH;
    int t = threadIdx.x;
    int lane = t & 31;
    int wid = t >> 5;

    float v[8];
    float run = 0.f;
    #pragma unroll
    for (int i = 0; i < 8; i++) {
        v[i] = c[(size_t)(b*SEQ + t*8 + i)*NH + h];
        run += v[i];
        v[i] = run;
    }
    float total = run;

    float inc = total;
    #pragma unroll
    for (int o = 1; o < 32; o <<= 1) {
        float n = __shfl_up_sync(0xffffffffu, inc, o);
        if (lane >= o) inc += n;
    }
    __shared__ float wsum[8];
    if (lane == 31) wsum[wid] = inc;
    __syncthreads();
    if (t == 0) {
        float a = 0.f;
        #pragma unroll
        for (int i = 0; i < 8; i++) { float tmp = wsum[i]; wsum[i] = a; a += tmp; }
    }
    __syncthreads();
    float off = wsum[wid] + (inc - total);

    #pragma unroll
    for (int i = 0; i < 8; i++)
        c[(size_t)(b*SEQ + t*8 + i)*NH + h] = v[i] + off;
}

__global__ __launch_bounds__(256) void flash_kernel(
    const float* __restrict__ Q, const float* __restrict__ K,
    const float* __restrict__ V, const float* __restrict__ Cd,
    float* __restrict__ O)
{
    extern __shared__ float sm[];
    float* Qt = sm;
    float* Kt = sm + 4096;
    float* Vs = sm + 8192;
    float* Ps = sm + 12288;
    float* ci = sm + 16384;
    float* cj = sm + 16448;

    int tid = threadIdx.x;
    int ty = tid >> 4;
    int tx = tid & 15;
    int r0 = ty*4;
    int c0 = tx*4;
    int b = blockIdx.z;
    int h = blockIdx.y;
    int i0 = blockIdx.x * 64;
    int qbase = b*SEQ + i0;
    const float scale = 0.125f;

    #pragma unroll
    for (int rep = 0; rep < 4; rep++) {
        int f = tid + rep*256;
        int r = f >> 4;
        int d4 = (f & 15) * 4;
        float4 qv = *(const float4*)(Q + (size_t)(qbase+r)*DM + h*64 + d4);
        Qt[(d4+0)*64 + r] = qv.x;
        Qt[(d4+1)*64 + r] = qv.y;
        Qt[(d4+2)*64 + r] = qv.z;
        Qt[(d4+3)*64 + r] = qv.w;
    }
    if (tid < 64) ci[tid] = Cd[(qbase+tid)*NH + h];

    float m_run[4];
    float l_run[4];
    float o[4][4];
    #pragma unroll
    for (int i = 0; i < 4; i++) {
        m_run[i] = -1e38f;
        l_run[i] = 0.f;
        #pragma unroll
        for (int j = 0; j < 4; j++) o[i][j] = 0.f;
    }

    for (int j0 = 0; j0 <= i0; j0 += 64) {
        __syncthreads();
        int kbase = b*SEQ + j0;
        #pragma unroll
        for (int rep = 0; rep < 4; rep++) {
            int f = tid + rep*256;
            int r = f >> 4;
            int d4 = (f & 15) * 4;
            float4 kv = *(const float4*)(K + (size_t)(kbase+r)*DM + h*64 + d4);
            Kt[(d4+0)*64 + r] = kv.x;
            Kt[(d4+1)*64 + r] = kv.y;
            Kt[(d4+2)*64 + r] = kv.z;
            Kt[(d4+3)*64 + r] = kv.w;
            float4 vv = *(const float4*)(V + (size_t)(kbase+r)*DM + h*64 + d4);
            *(float4*)(&Vs[r*64 + d4]) = vv;
        }
        if (tid < 64) cj[tid] = Cd[(kbase+tid)*NH + h];
        __syncthreads();

        float acc[4][4];
        #pragma unroll
        for (int i = 0; i < 4; i++) {
            #pragma unroll
            for (int j = 0; j < 4; j++) acc[i][j] = 0.f;
        }
        #pragma unroll
        for (int d = 0; d < 64; d++) {
            float4 qa = *(float4*)(&Qt[d*64 + r0]);
            float4 kb = *(float4*)(&Kt[d*64 + c0]);
            acc[0][0] += qa.x*kb.x; acc[0][1] += qa.x*kb.y; acc[0][2] += qa.x*kb.z; acc[0][3] += qa.x*kb.w;
            acc[1][0] += qa.y*kb.x; acc[1][1] += qa.y*kb.y; acc[1][2] += qa.y*kb.z; acc[1][3] += qa.y*kb.w;
            acc[2][0] += qa.z*kb.x; acc[2][1] += qa.z*kb.y; acc[2][2] += qa.z*kb.z; acc[2][3] += qa.z*kb.w;
            acc[3][0] += qa.w*kb.x; acc[3][1] += qa.w*kb.y; acc[3][2] += qa.w*kb.z; acc[3][3] += qa.w*kb.w;
        }

        bool diag = (j0 == i0);
        #pragma unroll
        for (int i = 0; i < 4; i++) {
            float crow = ci[r0+i];
            float s[4];
            #pragma unroll
            for (int j = 0; j < 4; j++) {
                s[j] = acc[i][j]*scale + crow - cj[c0+j];
                if (diag && (c0+j > r0+i)) s[j] = -1e30f;
            }
            float tm = fmaxf(fmaxf(s[0], s[1]), fmaxf(s[2], s[3]));
            #pragma unroll
            for (int off = 8; off; off >>= 1)
                tm = fmaxf(tm, __shfl_xor_sync(0xffffffffu, tm, off));
            float nm = fmaxf(m_run[i], tm);
            float p0 = __expf(s[0]-nm);
            float p1 = __expf(s[1]-nm);
            float p2 = __expf(s[2]-nm);
            float p3 = __expf(s[3]-nm);
            float tl = p0+p1+p2+p3;
            #pragma unroll
            for (int off = 8; off; off >>= 1)
                tl += __shfl_xor_sync(0xffffffffu, tl, off);
            float sc = __expf(m_run[i] - nm);
            l_run[i] = l_run[i]*sc + tl;
            m_run[i] = nm;
            #pragma unroll
            for (int j = 0; j < 4; j++) o[i][j] *= sc;
            *(float4*)(&Ps[(r0+i)*64 + c0]) = make_float4(p0, p1, p2, p3);
        }
        __syncthreads();

        #pragma unroll
        for (int kk = 0; kk < 64; kk++) {
            float4 bv = *(float4*)(&Vs[kk*64 + c0]);
            float a0 = Ps[(r0+0)*64 + kk];
            float a1 = Ps[(r0+1)*64 + kk];
            float a2 = Ps[(r0+2)*64 + kk];
            float a3 = Ps[(r0+3)*64 + kk];
            o[0][0] += a0*bv.x; o[0][1] += a0*bv.y; o[0][2] += a0*bv.z; o[0][3] += a0*bv.w;
            o[1][0] += a1*bv.x; o[1][1] += a1*bv.y; o[1][2] += a1*bv.z; o[1][3] += a1*bv.w;
            o[2][0] += a2*bv.x; o[2][1] += a2*bv.y; o[2][2] += a2*bv.z; o[2][3] += a2*bv.w;
            o[3][0] += a3*bv.x; o[3][1] += a3*bv.y; o[3][2] += a3*bv.z; o[3][3] += a3*bv.w;
        }
    }

    #pragma unroll
    for (int i = 0; i < 4; i++) {
        float inv = 1.0f / l_run[i];
        float4 ov = make_float4(o[i][0]*inv, o[i][1]*inv, o[i][2]*inv, o[i][3]*inv);
        *(float4*)(&O[(size_t)(qbase + r0 + i)*DM + h*64 + c0]) = ov;
    }
}

extern "C" void kernel_launch(void* const* d_in, const int* in_sizes, int n_in,
                              void* d_out, int out_size)
{
    const float* x     = (const float*)d_in[0];
    const float* ln1_g = (const float*)d_in[1];
    const float* ln1_b = (const float*)d_in[2];
    const float* wq    = (const float*)d_in[3];
    const float* bq    = (const float*)d_in[4];
    const float* wk    = (const float*)d_in[5];
    const float* bk    = (const float*)d_in[6];
    const float* wv    = (const float*)d_in[7];
    const float* bv    = (const float*)d_in[8];
    const float* wo    = (const float*)d_in[9];
    const float* bo    = (const float*)d_in[10];
    const float* wf    = (const float*)d_in[11];
    const float* bf    = (const float*)d_in[12];
    const float* ln2_g = (const float*)d_in[13];
    const float* ln2_b = (const float*)d_in[14];
    const float* w1    = (const float*)d_in[15];
    const float* b1    = (const float*)d_in[16];
    const float* w2    = (const float*)d_in[17];
    const float* b2    = (const float*)d_in[18];
    float* out = (float*)d_out;

    void *vh = 0, *vq = 0, *vk = 0, *vv = 0, *vc = 0, *vctx = 0, *vx1 = 0, *vh2 = 0, *vff = 0;
    cudaGetSymbolAddress(&vh,   g_h);
    cudaGetSymbolAddress(&vq,   g_q);
    cudaGetSymbolAddress(&vk,   g_k);
    cudaGetSymbolAddress(&vv,   g_v);
    cudaGetSymbolAddress(&vc,   g_c);
    cudaGetSymbolAddress(&vctx, g_ctx);
    cudaGetSymbolAddress(&vx1,  g_x1);
    cudaGetSymbolAddress(&vh2,  g_h2);
    cudaGetSymbolAddress(&vff,  g_ff);
    float* ph   = (float*)vh;
    float* pq   = (float*)vq;
    float* pk   = (float*)vk;
    float* pv   = (float*)vv;
    float* pc   = (float*)vc;
    float* pctx = (float*)vctx;
    float* px1  = (float*)vx1;
    float* ph2  = (float*)vh2;
    float* pff  = (float*)vff;

    ln_kernel<<<MR, 256>>>(x, ln1_g, ln1_b, ph);

    dim3 gD(DM/128, MR/128);
    bgemm_kernel<<<gD, 256>>>(ph, wq, bq, (const float*)0, pq, MR, DM, DM, 0);
    bgemm_kernel<<<gD, 256>>>(ph, wk, bk, (const float*)0, pk, MR, DM, DM, 0);
    bgemm_kernel<<<gD, 256>>>(ph, wv, bv, (const float*)0, pv, MR, DM, DM, 0);

    fgate_kernel<<<MR, 256>>>(ph, wf, bf, pc);
    cumsum_kernel<<<BSZ*NH, 256>>>(pc);

    const int FLASH_SMEM = (4*4096 + 128) * (int)sizeof(float);
    cudaFuncSetAttribute(flash_kernel, cudaFuncAttributeMaxDynamicSharedMemorySize, FLASH_SMEM);
    flash_kernel<<<dim3(SEQ/64, NH, BSZ), 256, FLASH_SMEM>>>(pq, pk, pv, pc, pctx);

    bgemm_kernel<<<gD, 256>>>(pctx, wo, bo, x, px1, MR, DM, DM, 1);

    ln_kernel<<<MR, 256>>>(px1, ln2_g, ln2_b, ph2);

    bgemm_kernel<<<dim3(DFF/128, MR/128), 256>>>(ph2, w1, b1, (const float*)0, pff, MR, DFF, DM, 2);

    bgemm_kernel<<<gD, 256>>>(pff, w2, b2, px1, out, MR, DM, DFF, 1);
}